// round 4
// baseline (speedup 1.0000x reference)
#include <cuda_runtime.h>
#include <math.h>

// HG2Vec fused loss, single persistent kernel, v4.
// Same decomposition as v3 (warp per (position, context-pair), 5 warps/pos):
//  - 14 register accumulators per warp (2 score + 12 info)
//  - info f4 buffer shrunk 6 -> 3 (two passes) to cut ~12 regs
//  - __launch_bounds__(160, 5): cap 80 regs -> 5 CTAs/SM = 25 warps/SM
//  - grid = 740 = 148 SMs * 5 resident CTAs: single persistent wave
//  - last-block-done deterministic reduction, counter self-resets (graph-safe)

#define DIM       300
#define ROWBYTES  1200u
#define NPOS      16384          // B*L
#define GRID      740            // 148 SMs * 5 resident CTAs
#define THREADS   160            // 5 warps = 1 position (2 contexts per warp)

__device__ float        g_partial[GRID];
__device__ unsigned int g_ticket = 0;

__global__ __launch_bounds__(THREADS, 5) void hg2vec_fused(
    const int*   __restrict__ pos_u,
    const int*   __restrict__ pos_v,
    const int*   __restrict__ info_v,
    const float* __restrict__ W_in,
    const float* __restrict__ W_out,
    const float* __restrict__ cmask,
    const float* __restrict__ sig_mask,
    const float* __restrict__ score_mask,
    float*       __restrict__ out)
{
    __shared__ float red[5][16];
    __shared__ float wloss[5];
    __shared__ bool  amLast;

    const int w    = threadIdx.x >> 5;     // 0..4 : context pair
    const int lane = threadIdx.x & 31;

    const char* __restrict__ Win_b  = (const char*)W_in;
    const char* __restrict__ Wout_b = (const char*)W_out;

    // per-warp context masks (2 contexts)
    const float cm0 = cmask[w * 2 + 0];
    const float cm1 = cmask[w * 2 + 1];

    // per-lane transcendental coefficients for the 14 terms this warp owns
    float t_sgn = 1.f, t_wt = 0.f;
    if (lane < 14) {
        if (lane < 2) { t_sgn = 1.f; t_wt = 1.f; }
        else {
            const int i = (lane - 2) % 6;
            t_sgn = sig_mask[i];
            t_wt  = score_mask[i];
        }
    }

    float acc_loss = 0.f;

    for (int p = blockIdx.x; p < NPOS; p += GRID) {
        // ---- gather indices -> 32-bit byte offsets ----
        const unsigned puo  = (unsigned)pos_u[p] * ROWBYTES;
        const unsigned pvo0 = (unsigned)pos_v[p * 10 + w * 2 + 0] * ROWBYTES;
        const unsigned pvo1 = (unsigned)pos_v[p * 10 + w * 2 + 1] * ROWBYTES;
        unsigned ivo[6];
#pragma unroll
        for (int i = 0; i < 6; i++)
            ivo[i] = (unsigned)info_v[p * 6 + i] * ROWBYTES;

        // ---- 14 accumulators ----
        float sc0 = 0.f, sc1 = 0.f;
        float ai[12];
#pragma unroll
        for (int k = 0; k < 12; k++) ai[k] = 0.f;

#pragma unroll
        for (int jj = 0; jj < 3; jj++) {
            const int j = lane + jj * 32;
            if (j < 75) {
                const unsigned jb = (unsigned)j * 16u;
                // front-batch the 5 always-needed rows
                const float4 t4 = *(const float4*)(Wout_b + puo  + jb);
                const float4 a0 = *(const float4*)(Win_b  + pvo0 + jb);
                const float4 a1 = *(const float4*)(Win_b  + pvo1 + jb);
                const float4 b0 = *(const float4*)(Wout_b + pvo0 + jb);
                const float4 b1 = *(const float4*)(Wout_b + pvo1 + jb);

                sc0 += a0.x * t4.x + a0.y * t4.y + a0.z * t4.z + a0.w * t4.w;
                sc1 += a1.x * t4.x + a1.y * t4.y + a1.z * t4.z + a1.w * t4.w;

                // info rows in two passes of 3 (register diet: 3-deep buffer)
#pragma unroll
                for (int h = 0; h < 2; h++) {
                    float4 f4[3];
#pragma unroll
                    for (int i = 0; i < 3; i++)
                        f4[i] = *(const float4*)(Win_b + ivo[h * 3 + i] + jb);
#pragma unroll
                    for (int i = 0; i < 3; i++) {
                        const int k = h * 3 + i;
                        ai[k]     += b0.x * f4[i].x + b0.y * f4[i].y
                                   + b0.z * f4[i].z + b0.w * f4[i].w;
                        ai[6 + k] += b1.x * f4[i].x + b1.y * f4[i].y
                                   + b1.z * f4[i].z + b1.w * f4[i].w;
                    }
                }
            }
        }

        // ---- butterfly reduce 14 accumulators across warp ----
#pragma unroll
        for (int off = 16; off; off >>= 1) {
            sc0 += __shfl_xor_sync(0xffffffffu, sc0, off);
            sc1 += __shfl_xor_sync(0xffffffffu, sc1, off);
#pragma unroll
            for (int k = 0; k < 12; k++)
                ai[k] += __shfl_xor_sync(0xffffffffu, ai[k], off);
        }

        // ---- stage to smem, eval transcendentals warp-parallel ----
        if (lane == 0) {
            red[w][0] = sc0 * cm0;
            red[w][1] = sc1 * cm1;
#pragma unroll
            for (int k = 0; k < 12; k++) red[w][2 + k] = ai[k];
        }
        __syncwarp();

        if (lane < 14) {
            const float v = red[w][lane];
            const float x = fminf(fmaxf(v, -10.f), 10.f) * t_sgn;
            acc_loss += log1pf(expf(-x)) * t_wt;
        }
        __syncwarp();   // red[w] reused next iteration
    }

    // ---- block reduction ----
#pragma unroll
    for (int off = 16; off; off >>= 1)
        acc_loss += __shfl_xor_sync(0xffffffffu, acc_loss, off);
    if (lane == 0) wloss[w] = acc_loss;
    __syncthreads();

    if (threadIdx.x == 0) {
        float s = wloss[0] + wloss[1] + wloss[2] + wloss[3] + wloss[4];
        g_partial[blockIdx.x] = s;
        __threadfence();
        unsigned t = atomicAdd(&g_ticket, 1u);
        amLast = (t == GRID - 1);
    }
    __syncthreads();

    // ---- last block: deterministic fixed-order final sum ----
    if (amLast) {
        __shared__ float fs[THREADS];
        float v = 0.f;
        for (int i = threadIdx.x; i < GRID; i += THREADS)
            v += __ldcg(&g_partial[i]);
        fs[threadIdx.x] = v;
        __syncthreads();
#pragma unroll
        for (int st = 128; st; st >>= 1) {
            if (threadIdx.x < st && threadIdx.x + st < THREADS)
                fs[threadIdx.x] += fs[threadIdx.x + st];
            __syncthreads();
        }
        if (threadIdx.x == 0) {
            out[0] = fs[0];
            g_ticket = 0;            // reset for next graph replay
            __threadfence();
        }
    }
}

extern "C" void kernel_launch(void* const* d_in, const int* in_sizes, int n_in,
                              void* d_out, int out_size)
{
    const int*   pos_u  = (const int*)  d_in[0];
    const int*   pos_v  = (const int*)  d_in[1];
    const int*   info_v = (const int*)  d_in[2];
    const float* W_in   = (const float*)d_in[3];
    const float* W_out  = (const float*)d_in[4];
    const float* cmask  = (const float*)d_in[5];
    const float* sigm   = (const float*)d_in[6];
    const float* smask  = (const float*)d_in[7];

    hg2vec_fused<<<GRID, THREADS>>>(pos_u, pos_v, info_v, W_in, W_out,
                                    cmask, sigm, smask, (float*)d_out);
}

// round 5
// speedup vs baseline: 1.7189x; 1.7189x over previous
#include <cuda_runtime.h>
#include <math.h>

// HG2Vec fused loss, single persistent kernel, v5 (= v3 mainloop + cheap epilogue).
// Decomposition: warp per (position, context-pair), 5 warps/block = 1 position.
//  - 14 register accumulators (2 score + 12 info), 6-deep f4 buffer (v3 proven)
//  - scattered 16-value warp reduction: 31 shfl instead of 70, no smem staging;
//    sum of value k lands on lanes {2k,2k+1}, even lane evaluates the term
//  - fast softplus: __logf(1+__expf(-x))  (MUFU; ~1e-6 rel on final scalar)
//  - next-iteration index prefetch for pos_u/pos_v (hide idx->row load chain)
//  - __launch_bounds__(160,4): 4 CTAs/SM, grid 592 = one persistent wave
//  - last-block-done deterministic reduction, counter self-resets (graph-safe)

#define DIM       300
#define ROWBYTES  1200u
#define NPOS      16384          // B*L
#define GRID      592            // 148 SMs * 4 resident CTAs
#define THREADS   160            // 5 warps = 1 position (2 contexts per warp)

__device__ float        g_partial[GRID];
__device__ unsigned int g_ticket = 0;

__global__ __launch_bounds__(THREADS, 4) void hg2vec_fused(
    const int*   __restrict__ pos_u,
    const int*   __restrict__ pos_v,
    const int*   __restrict__ info_v,
    const float* __restrict__ W_in,
    const float* __restrict__ W_out,
    const float* __restrict__ cmask,
    const float* __restrict__ sig_mask,
    const float* __restrict__ score_mask,
    float*       __restrict__ out)
{
    __shared__ float wloss[5];
    __shared__ bool  amLast;

    const int w    = threadIdx.x >> 5;     // 0..4 : context pair
    const int lane = threadIdx.x & 31;

    const char* __restrict__ Win_b  = (const char*)W_in;
    const char* __restrict__ Wout_b = (const char*)W_out;

    // ---- per-lane term coefficients; value index k = lane>>1 ----
    //   k 0..1  : score terms  (pre = cmask, sgn = 1, wt = 1)
    //   k 2..13 : info terms,  i = (k-2)%6 (pre = 1, sgn = sig[i], wt = smask[i])
    //   odd lanes & k>=14 : wt = 0 (duplicate / padding)
    const int k = lane >> 1;
    float t_pre = 1.f, t_sgn = 1.f, t_wt = 0.f;
    if (((lane & 1) == 0) && k < 14) {
        if (k < 2) { t_pre = cmask[w * 2 + k]; t_sgn = 1.f; t_wt = 1.f; }
        else {
            const int i = (k - 2) % 6;
            t_sgn = sig_mask[i];
            t_wt  = score_mask[i];
        }
    }

    float acc_loss = 0.f;

    int p = blockIdx.x;
    // prime the index prefetch pipeline
    int nxt_pu  = pos_u[p];
    int nxt_pv0 = pos_v[p * 10 + w * 2 + 0];
    int nxt_pv1 = pos_v[p * 10 + w * 2 + 1];

    while (p < NPOS) {
        const unsigned puo  = (unsigned)nxt_pu  * ROWBYTES;
        const unsigned pvo0 = (unsigned)nxt_pv0 * ROWBYTES;
        const unsigned pvo1 = (unsigned)nxt_pv1 * ROWBYTES;
        unsigned ivo[6];
#pragma unroll
        for (int i = 0; i < 6; i++)
            ivo[i] = (unsigned)info_v[p * 6 + i] * ROWBYTES;

        // prefetch next iteration's indices (overlaps with the FMA loop below)
        const int pn = p + GRID;
        if (pn < NPOS) {
            nxt_pu  = pos_u[pn];
            nxt_pv0 = pos_v[pn * 10 + w * 2 + 0];
            nxt_pv1 = pos_v[pn * 10 + w * 2 + 1];
        }

        // ---- 14 accumulators ----
        float sc0 = 0.f, sc1 = 0.f;
        float ai[12];
#pragma unroll
        for (int q = 0; q < 12; q++) ai[q] = 0.f;

#pragma unroll
        for (int jj = 0; jj < 3; jj++) {
            const int j = lane + jj * 32;
            if (j < 75) {
                const unsigned jb = (unsigned)j * 16u;
                const float4 t4 = *(const float4*)(Wout_b + puo + jb);
                float4 f4[6];
#pragma unroll
                for (int i = 0; i < 6; i++)
                    f4[i] = *(const float4*)(Win_b + ivo[i] + jb);

                const float4 a0 = *(const float4*)(Win_b + pvo0 + jb);
                const float4 a1 = *(const float4*)(Win_b + pvo1 + jb);
                const float4 b0 = *(const float4*)(Wout_b + pvo0 + jb);
                const float4 b1 = *(const float4*)(Wout_b + pvo1 + jb);

                sc0 += a0.x * t4.x + a0.y * t4.y + a0.z * t4.z + a0.w * t4.w;
                sc1 += a1.x * t4.x + a1.y * t4.y + a1.z * t4.z + a1.w * t4.w;
#pragma unroll
                for (int i = 0; i < 6; i++) {
                    ai[i]     += b0.x * f4[i].x + b0.y * f4[i].y
                               + b0.z * f4[i].z + b0.w * f4[i].w;
                    ai[6 + i] += b1.x * f4[i].x + b1.y * f4[i].y
                               + b1.z * f4[i].z + b1.w * f4[i].w;
                }
            }
        }

        // ---- scattered 16-value warp reduction (31 shfl) ----
        // v[16] = {sc0, sc1, ai[0..11], 0, 0}; result for value q on lanes {2q,2q+1}
        {
            float v0[8], v1[4], v2[2], v3;
            // round 0, off=16 : merge (q, q+8) selecting on lane bit 4
            {
                float a, b;
                a = sc0   + __shfl_xor_sync(0xffffffffu, sc0,   16);
                b = ai[6] + __shfl_xor_sync(0xffffffffu, ai[6], 16);
                v0[0] = (lane & 16) ? b : a;
                a = sc1   + __shfl_xor_sync(0xffffffffu, sc1,   16);
                b = ai[7] + __shfl_xor_sync(0xffffffffu, ai[7], 16);
                v0[1] = (lane & 16) ? b : a;
#pragma unroll
                for (int q = 0; q < 4; q++) {
                    a = ai[q]     + __shfl_xor_sync(0xffffffffu, ai[q],     16);
                    b = ai[q + 8] + __shfl_xor_sync(0xffffffffu, ai[q + 8], 16);
                    v0[2 + q] = (lane & 16) ? b : a;
                }
                a = ai[4] + __shfl_xor_sync(0xffffffffu, ai[4], 16);
                v0[6] = (lane & 16) ? 0.f : a;          // pair is padding 0
                a = ai[5] + __shfl_xor_sync(0xffffffffu, ai[5], 16);
                v0[7] = (lane & 16) ? 0.f : a;
            }
            // round 1, off=8 : merge (q, q+4) on bit 3
#pragma unroll
            for (int q = 0; q < 4; q++) {
                const float a = v0[q]     + __shfl_xor_sync(0xffffffffu, v0[q],     8);
                const float b = v0[q + 4] + __shfl_xor_sync(0xffffffffu, v0[q + 4], 8);
                v1[q] = (lane & 8) ? b : a;
            }
            // round 2, off=4 : merge (q, q+2) on bit 2
#pragma unroll
            for (int q = 0; q < 2; q++) {
                const float a = v1[q]     + __shfl_xor_sync(0xffffffffu, v1[q],     4);
                const float b = v1[q + 2] + __shfl_xor_sync(0xffffffffu, v1[q + 2], 4);
                v2[q] = (lane & 4) ? b : a;
            }
            // round 3, off=2 : merge (0,1) on bit 1
            {
                const float a = v2[0] + __shfl_xor_sync(0xffffffffu, v2[0], 2);
                const float b = v2[1] + __shfl_xor_sync(0xffffffffu, v2[1], 2);
                v3 = (lane & 2) ? b : a;
            }
            // round 4, off=1 : final pair sum
            v3 += __shfl_xor_sync(0xffffffffu, v3, 1);
            // lane L holds full sum of value index k = (b4*8 + b3*4 + b2*2 + b1) = L>>1

            // ---- evaluate loss term in place (even lanes only, via t_wt) ----
            const float x = fminf(fmaxf(v3 * t_pre, -10.f), 10.f) * t_sgn;
            acc_loss += __logf(1.f + __expf(-x)) * t_wt;
        }

        p = pn;
    }

    // ---- block reduction ----
#pragma unroll
    for (int off = 16; off; off >>= 1)
        acc_loss += __shfl_xor_sync(0xffffffffu, acc_loss, off);
    if (lane == 0) wloss[w] = acc_loss;
    __syncthreads();

    if (threadIdx.x == 0) {
        float s = wloss[0] + wloss[1] + wloss[2] + wloss[3] + wloss[4];
        g_partial[blockIdx.x] = s;
        __threadfence();
        unsigned t = atomicAdd(&g_ticket, 1u);
        amLast = (t == GRID - 1);
    }
    __syncthreads();

    // ---- last block: deterministic fixed-order final sum ----
    if (amLast) {
        __shared__ float fs[THREADS];
        float v = 0.f;
        for (int i = threadIdx.x; i < GRID; i += THREADS)
            v += __ldcg(&g_partial[i]);
        fs[threadIdx.x] = v;
        __syncthreads();
#pragma unroll
        for (int st = 128; st; st >>= 1) {
            if (threadIdx.x < st && threadIdx.x + st < THREADS)
                fs[threadIdx.x] += fs[threadIdx.x + st];
            __syncthreads();
        }
        if (threadIdx.x == 0) {
            out[0] = fs[0];
            g_ticket = 0;            // reset for next graph replay
            __threadfence();
        }
    }
}

extern "C" void kernel_launch(void* const* d_in, const int* in_sizes, int n_in,
                              void* d_out, int out_size)
{
    const int*   pos_u  = (const int*)  d_in[0];
    const int*   pos_v  = (const int*)  d_in[1];
    const int*   info_v = (const int*)  d_in[2];
    const float* W_in   = (const float*)d_in[3];
    const float* W_out  = (const float*)d_in[4];
    const float* cmask  = (const float*)d_in[5];
    const float* sigm   = (const float*)d_in[6];
    const float* smask  = (const float*)d_in[7];

    hg2vec_fused<<<GRID, THREADS>>>(pos_u, pos_v, info_v, W_in, W_out,
                                    cmask, sigm, smask, (float*)d_out);
}

// round 6
// speedup vs baseline: 1.8047x; 1.0499x over previous
#include <cuda_runtime.h>
#include <math.h>

// HG2Vec fused loss, single persistent kernel, v6 = v5 + cross-iteration pipelining.
// Decomposition: warp per (position, context-pair), 5 warps/block = 1 position.
//  - 14 register accumulators (2 score + 12 info)
//  - software pipeline: next position's chunk-0 rows (11 float4) are loaded
//    BEFORE the butterfly/loss epilogue, reusing the chunk buffers (dead there),
//    so DRAM stays busy during the shfl/MUFU phase of every iteration
//  - all next-iteration indices (pos_u, pos_v, info_v) loaded at iteration top
//  - scattered 16-value warp reduction (31 shfl), fast softplus (MUFU)
//  - __launch_bounds__(160,4): 4 CTAs/SM, grid 592 = one persistent wave
//  - last-block-done deterministic reduction, counter self-resets (graph-safe)

#define DIM       300
#define ROWBYTES  1200u
#define NPOS      16384          // B*L
#define GRID      592            // 148 SMs * 4 resident CTAs
#define THREADS   160            // 5 warps = 1 position (2 contexts per warp)

__device__ float        g_partial[GRID];
__device__ unsigned int g_ticket = 0;

// dot-accumulate one chunk (t4,a0,a1,b0,b1,f4[6]) into (sc0,sc1,ai[12])
#define CHUNK_FMA()                                                         \
    do {                                                                    \
        sc0 += a0.x * t4.x + a0.y * t4.y + a0.z * t4.z + a0.w * t4.w;       \
        sc1 += a1.x * t4.x + a1.y * t4.y + a1.z * t4.z + a1.w * t4.w;       \
        _Pragma("unroll")                                                   \
        for (int i = 0; i < 6; i++) {                                       \
            ai[i]     += b0.x * f4[i].x + b0.y * f4[i].y                    \
                       + b0.z * f4[i].z + b0.w * f4[i].w;                   \
            ai[6 + i] += b1.x * f4[i].x + b1.y * f4[i].y                    \
                       + b1.z * f4[i].z + b1.w * f4[i].w;                   \
        }                                                                   \
    } while (0)

#define CHUNK_LOAD(JB)                                                      \
    do {                                                                    \
        t4 = *(const float4*)(Wout_b + puo  + (JB));                        \
        a0 = *(const float4*)(Win_b  + pvo0 + (JB));                        \
        a1 = *(const float4*)(Win_b  + pvo1 + (JB));                        \
        b0 = *(const float4*)(Wout_b + pvo0 + (JB));                        \
        b1 = *(const float4*)(Wout_b + pvo1 + (JB));                        \
        _Pragma("unroll")                                                   \
        for (int i = 0; i < 6; i++)                                         \
            f4[i] = *(const float4*)(Win_b + ivo[i] + (JB));                \
    } while (0)

__global__ __launch_bounds__(THREADS, 4) void hg2vec_fused(
    const int*   __restrict__ pos_u,
    const int*   __restrict__ pos_v,
    const int*   __restrict__ info_v,
    const float* __restrict__ W_in,
    const float* __restrict__ W_out,
    const float* __restrict__ cmask,
    const float* __restrict__ sig_mask,
    const float* __restrict__ score_mask,
    float*       __restrict__ out)
{
    __shared__ float wloss[5];
    __shared__ bool  amLast;

    const int w    = threadIdx.x >> 5;     // 0..4 : context pair
    const int lane = threadIdx.x & 31;

    const char* __restrict__ Win_b  = (const char*)W_in;
    const char* __restrict__ Wout_b = (const char*)W_out;

    // ---- per-lane term coefficients; value index k = lane>>1 ----
    const int kk = lane >> 1;
    float t_pre = 1.f, t_sgn = 1.f, t_wt = 0.f;
    if (((lane & 1) == 0) && kk < 14) {
        if (kk < 2) { t_pre = cmask[w * 2 + kk]; t_sgn = 1.f; t_wt = 1.f; }
        else {
            const int i = (kk - 2) % 6;
            t_sgn = sig_mask[i];
            t_wt  = score_mask[i];
        }
    }

    const unsigned jb0 = (unsigned)lane * 16u;          // chunk0 byte offset
    const unsigned jb1 = jb0 + 512u;                    // chunk1
    const unsigned jb2 = jb0 + 1024u;                   // chunk2 (lane<11)

    float acc_loss = 0.f;

    int p = blockIdx.x;

    // ---- prime the pipeline: indices, offsets, chunk-0 rows for first p ----
    unsigned puo  = (unsigned)pos_u[p] * ROWBYTES;
    unsigned pvo0 = (unsigned)pos_v[p * 10 + w * 2 + 0] * ROWBYTES;
    unsigned pvo1 = (unsigned)pos_v[p * 10 + w * 2 + 1] * ROWBYTES;
    unsigned ivo[6];
#pragma unroll
    for (int i = 0; i < 6; i++)
        ivo[i] = (unsigned)info_v[p * 6 + i] * ROWBYTES;

    float4 t4, a0, a1, b0, b1, f4[6];
    CHUNK_LOAD(jb0);

    while (p < NPOS) {
        const int pn = p + GRID;
        const int ps = (pn < NPOS) ? pn : 0;   // clamped: branch-free tail

        // ---- next-iteration index loads (fully overlapped with the chunks) ----
        const int n_pu  = pos_u[ps];
        const int n_pv0 = pos_v[ps * 10 + w * 2 + 0];
        const int n_pv1 = pos_v[ps * 10 + w * 2 + 1];
        int n_iv[6];
#pragma unroll
        for (int i = 0; i < 6; i++) n_iv[i] = info_v[ps * 6 + i];

        // ---- accumulators ----
        float sc0 = 0.f, sc1 = 0.f;
        float ai[12];
#pragma unroll
        for (int q = 0; q < 12; q++) ai[q] = 0.f;

        // chunk 0: preloaded registers
        CHUNK_FMA();
        // chunk 1: j = lane+32 (always < 75)
        CHUNK_LOAD(jb1);
        CHUNK_FMA();
        // chunk 2: j = lane+64, only lanes 0..10
        if (lane < 11) {
            CHUNK_LOAD(jb2);
            CHUNK_FMA();
        }

        // ---- advance offsets and PRELOAD next position's chunk 0 ----
        // (these loads are in flight during the butterfly + loss below)
        puo  = (unsigned)n_pu  * ROWBYTES;
        pvo0 = (unsigned)n_pv0 * ROWBYTES;
        pvo1 = (unsigned)n_pv1 * ROWBYTES;
#pragma unroll
        for (int i = 0; i < 6; i++) ivo[i] = (unsigned)n_iv[i] * ROWBYTES;
        CHUNK_LOAD(jb0);

        // ---- scattered 16-value warp reduction (31 shfl) ----
        // v[16] = {sc0, sc1, ai[0..11], 0, 0}; sum of value q lands on lanes {2q,2q+1}
        {
            float v0[8], v1[4], v2[2], v3;
            {
                float a, b;
                a = sc0   + __shfl_xor_sync(0xffffffffu, sc0,   16);
                b = ai[6] + __shfl_xor_sync(0xffffffffu, ai[6], 16);
                v0[0] = (lane & 16) ? b : a;
                a = sc1   + __shfl_xor_sync(0xffffffffu, sc1,   16);
                b = ai[7] + __shfl_xor_sync(0xffffffffu, ai[7], 16);
                v0[1] = (lane & 16) ? b : a;
#pragma unroll
                for (int q = 0; q < 4; q++) {
                    a = ai[q]     + __shfl_xor_sync(0xffffffffu, ai[q],     16);
                    b = ai[q + 8] + __shfl_xor_sync(0xffffffffu, ai[q + 8], 16);
                    v0[2 + q] = (lane & 16) ? b : a;
                }
                a = ai[4] + __shfl_xor_sync(0xffffffffu, ai[4], 16);
                v0[6] = (lane & 16) ? 0.f : a;
                a = ai[5] + __shfl_xor_sync(0xffffffffu, ai[5], 16);
                v0[7] = (lane & 16) ? 0.f : a;
            }
#pragma unroll
            for (int q = 0; q < 4; q++) {
                const float a = v0[q]     + __shfl_xor_sync(0xffffffffu, v0[q],     8);
                const float b = v0[q + 4] + __shfl_xor_sync(0xffffffffu, v0[q + 4], 8);
                v1[q] = (lane & 8) ? b : a;
            }
#pragma unroll
            for (int q = 0; q < 2; q++) {
                const float a = v1[q]     + __shfl_xor_sync(0xffffffffu, v1[q],     4);
                const float b = v1[q + 2] + __shfl_xor_sync(0xffffffffu, v1[q + 2], 4);
                v2[q] = (lane & 4) ? b : a;
            }
            {
                const float a = v2[0] + __shfl_xor_sync(0xffffffffu, v2[0], 2);
                const float b = v2[1] + __shfl_xor_sync(0xffffffffu, v2[1], 2);
                v3 = (lane & 2) ? b : a;
            }
            v3 += __shfl_xor_sync(0xffffffffu, v3, 1);

            const float x = fminf(fmaxf(v3 * t_pre, -10.f), 10.f) * t_sgn;
            acc_loss += __logf(1.f + __expf(-x)) * t_wt;
        }

        p = pn;
    }

    // ---- block reduction ----
#pragma unroll
    for (int off = 16; off; off >>= 1)
        acc_loss += __shfl_xor_sync(0xffffffffu, acc_loss, off);
    if (lane == 0) wloss[w] = acc_loss;
    __syncthreads();

    if (threadIdx.x == 0) {
        float s = wloss[0] + wloss[1] + wloss[2] + wloss[3] + wloss[4];
        g_partial[blockIdx.x] = s;
        __threadfence();
        unsigned t = atomicAdd(&g_ticket, 1u);
        amLast = (t == GRID - 1);
    }
    __syncthreads();

    // ---- last block: deterministic fixed-order final sum ----
    if (amLast) {
        __shared__ float fs[THREADS];
        float v = 0.f;
        for (int i = threadIdx.x; i < GRID; i += THREADS)
            v += __ldcg(&g_partial[i]);
        fs[threadIdx.x] = v;
        __syncthreads();
#pragma unroll
        for (int st = 128; st; st >>= 1) {
            if (threadIdx.x < st && threadIdx.x + st < THREADS)
                fs[threadIdx.x] += fs[threadIdx.x + st];
            __syncthreads();
        }
        if (threadIdx.x == 0) {
            out[0] = fs[0];
            g_ticket = 0;            // reset for next graph replay
            __threadfence();
        }
    }
}

extern "C" void kernel_launch(void* const* d_in, const int* in_sizes, int n_in,
                              void* d_out, int out_size)
{
    const int*   pos_u  = (const int*)  d_in[0];
    const int*   pos_v  = (const int*)  d_in[1];
    const int*   info_v = (const int*)  d_in[2];
    const float* W_in   = (const float*)d_in[3];
    const float* W_out  = (const float*)d_in[4];
    const float* cmask  = (const float*)d_in[5];
    const float* sigm   = (const float*)d_in[6];
    const float* smask  = (const float*)d_in[7];

    hg2vec_fused<<<GRID, THREADS>>>(pos_u, pos_v, info_v, W_in, W_out,
                                    cmask, sigm, smask, (float*)d_out);
}